// round 3
// baseline (speedup 1.0000x reference)
#include <cuda_runtime.h>
#include <cuda_bf16.h>

// diag-embed: out[i, j, k] = (j == k) ? x[i, j] : 0
// x: [8192, 176] fp32, out: [8192, 176, 176] fp32 (~1.015 GB of stores).
//
// R3: all index math hoisted out of the loop. Each thread owns a fixed chunk
// position q = tid % 44 within a 176-float output row; rows advance by a
// grid-stride chosen to be a multiple of 176 (5808 = 33*176), so the
// diagonal predicate / lane of every thread is loop-invariant. Steady-state
// body: predicated L2-hot LDG (1/44 threads) + STG.128 + pointer adds.

#define D_MODEL 176u
#define CPR 44u                 // float4 chunks per output row
#define THREADS 352u            // 8 rows per block per iteration (352/44)
#define BLOCKS 726u             // 726*8 = 5808 = 33*176  -> row phase invariant

__global__ __launch_bounds__(THREADS) void diag_embed_kernel(
        const float* __restrict__ x,
        float4* __restrict__ out,
        unsigned n_rows) {
    const unsigned t  = threadIdx.x;
    const unsigned q  = t % CPR;          // chunk index within row (invariant)
    const unsigned lr = t / CPR;          // local row within block (0..7)

    unsigned rowg = blockIdx.x * (THREADS / CPR) + lr;
    const unsigned stride_rows = BLOCKS * (THREADS / CPR);   // 5808

    // stride_rows % 176 == 0  =>  row (diag position) is constant for this thread
    const unsigned row  = rowg % D_MODEL;
    const bool     diag = (q == (row >> 2));
    const unsigned lane = row & 3u;

    const float* xp = x + rowg;
    float4*      p  = out + (size_t)rowg * CPR + q;

    #pragma unroll 4
    for (; rowg < n_rows; rowg += stride_rows) {
        float4 v = make_float4(0.f, 0.f, 0.f, 0.f);
        if (diag) {
            ((float*)&v)[lane] = __ldg(xp);   // L2-hot: x is only 5.8 MB
        }
        *p = v;
        p  += (size_t)stride_rows * CPR;
        xp += stride_rows;
    }
}

extern "C" void kernel_launch(void* const* d_in, const int* in_sizes, int n_in,
                              void* d_out, int out_size) {
    const float* x = (const float*)d_in[0];
    float4* out = (float4*)d_out;

    unsigned n_rows = (unsigned)(out_size / (int)D_MODEL);   // 1,441,792 rows

    diag_embed_kernel<<<BLOCKS, THREADS>>>(x, out, n_rows);
}

// round 4
// speedup vs baseline: 1.1928x; 1.1928x over previous
#include <cuda_runtime.h>
#include <cuda_bf16.h>

// diag-embed: out[i, j, k] = (j == k) ? x[i, j] : 0
// x: [8192, 176] fp32, out: [8192, 176, 176] fp32 (~1.015 GB of stores).
//
// R4: R2's proven concurrency shape (1184 blocks x 256 thr = exactly 8
// blocks/SM, 95% occ) + three store-path fixes:
//   - branchless diagonal insertion (unconditional L2-hot LDG + 4 selects)
//     -> no BSSY/BSYNC divergence per iteration
//   - unroll 8 for more independent STG.128s in flight
//   - __stcs streaming stores (write-once data, evict-first)

#define D_MODEL 176u
#define CPR 44u            // float4 chunks per output row
#define BLOCKS 1184u       // 148 SMs * 8 blocks -> perfectly balanced
#define THREADS 256u

__global__ __launch_bounds__(THREADS) void diag_embed_kernel(
        const float* __restrict__ x,
        float4* __restrict__ out,
        unsigned n4) {
    const unsigned stride = BLOCKS * THREADS;
    unsigned g = blockIdx.x * THREADS + threadIdx.x;

    #pragma unroll 8
    for (; g < n4; g += stride) {
        unsigned rowg = g / CPR;                 // 32-bit magic div
        unsigned q    = g - rowg * CPR;          // chunk within row
        unsigned row  = rowg % D_MODEL;          // diag position in row

        // Unconditional: warp's chunks span <=2 rows -> 1-2 L2-hot sectors.
        float xv = __ldg(x + rowg);

        unsigned c0 = q * 4u;                    // column of v.x
        float4 v;
        v.x = (c0        == row) ? xv : 0.f;
        v.y = (c0 + 1u   == row) ? xv : 0.f;
        v.z = (c0 + 2u   == row) ? xv : 0.f;
        v.w = (c0 + 3u   == row) ? xv : 0.f;

        __stcs(out + g, v);                      // streaming store
    }
}

extern "C" void kernel_launch(void* const* d_in, const int* in_sizes, int n_in,
                              void* d_out, int out_size) {
    const float* x = (const float*)d_in[0];
    float4* out = (float4*)d_out;

    unsigned n4 = (unsigned)(out_size / 4);      // 63,438,848 float4 chunks

    diag_embed_kernel<<<BLOCKS, THREADS>>>(x, out, n4);
}